// round 1
// baseline (speedup 1.0000x reference)
#include <cuda_runtime.h>

#define NN 1024
#define HH 128
#define TI 4   // rows per block in attn kernel

// Scratch (device globals: no allocations allowed)
__device__ __align__(16) float g_q[NN * HH];
__device__ __align__(16) float g_k[NN * HH];
__device__ __align__(16) float g_v[NN * HH];
__device__ __align__(16) float4 g_abcg[HH];
__device__ float g_c0d;

// ---------------------------------------------------------------------------
// Fold coord path:  coord_w[i,j] = sum_h relu(a_h*dx+b_h*dy+c_h)*g_h + c0
//   g = Wc @ We2  (length H), c0 = Wc . be2 + bc
// ---------------------------------------------------------------------------
__global__ void fold_kernel(const float* __restrict__ We1, const float* __restrict__ be1,
                            const float* __restrict__ We2, const float* __restrict__ be2,
                            const float* __restrict__ Wc,  const float* __restrict__ bc) {
    int h = threadIdx.x;
    float g = 0.f;
    for (int e = 0; e < HH; ++e) g = fmaf(Wc[e], We2[e * HH + h], g);
    g_abcg[h] = make_float4(We1[h * 2 + 0], We1[h * 2 + 1], be1[h], g);
    if (h == 0) {
        float c0 = bc[0];
        for (int e = 0; e < HH; ++e) c0 = fmaf(Wc[e], be2[e], c0);
        g_c0d = c0;
    }
}

// ---------------------------------------------------------------------------
// QKV: q = (h@Wq^T + bq) * 1/sqrt(H),  k = h@Wk^T + bk,  v = h@Wv^T + bv
// 128 blocks x 8 rows, 384 threads: thread o owns one output column of q|k|v.
// ---------------------------------------------------------------------------
__global__ __launch_bounds__(384) void qkv_kernel(
    const float* __restrict__ hin,
    const float* __restrict__ Wq, const float* __restrict__ bq,
    const float* __restrict__ Wk, const float* __restrict__ bk,
    const float* __restrict__ Wv, const float* __restrict__ bv) {
    __shared__ float hs[8][HH];
    int r0 = blockIdx.x * 8;
    for (int idx = threadIdx.x; idx < 8 * HH; idx += 384)
        hs[idx >> 7][idx & 127] = hin[r0 * HH + idx];
    __syncthreads();

    int o = threadIdx.x;
    const float* W; float bias; float* dst; int col; float scale;
    if (o < 128)      { W = Wq + o * HH;         bias = bq[o];       dst = g_q; col = o;       scale = 0.08838834764831845f; }
    else if (o < 256) { W = Wk + (o - 128) * HH; bias = bk[o - 128]; dst = g_k; col = o - 128; scale = 1.0f; }
    else              { W = Wv + (o - 256) * HH; bias = bv[o - 256]; dst = g_v; col = o - 256; scale = 1.0f; }

    float acc[8];
#pragma unroll
    for (int r = 0; r < 8; ++r) acc[r] = bias;

    const float4* W4 = (const float4*)W;
#pragma unroll 8
    for (int c4 = 0; c4 < 32; ++c4) {
        float4 w = W4[c4];
#pragma unroll
        for (int r = 0; r < 8; ++r) {
            float4 hv = ((const float4*)&hs[r][0])[c4];
            acc[r] = fmaf(hv.x, w.x, acc[r]);
            acc[r] = fmaf(hv.y, w.y, acc[r]);
            acc[r] = fmaf(hv.z, w.z, acc[r]);
            acc[r] = fmaf(hv.w, w.w, acc[r]);
        }
    }
#pragma unroll
    for (int r = 0; r < 8; ++r) dst[(r0 + r) * HH + col] = acc[r] * scale;
}

// ---------------------------------------------------------------------------
// Fused attention + coord diffusion. One warp per output row, TI rows/block.
// ---------------------------------------------------------------------------
__global__ __launch_bounds__(128) void attn_kernel(
    const float* __restrict__ hin,
    const float* __restrict__ xin,
    float* __restrict__ out) {
    __shared__ float  qs[TI][132];      // padded: stride 132 floats (33 float4)
    __shared__ float  kvs[32][132];     // k/v tile, conflict-free LDS.128
    __shared__ float  ss[TI][NN];       // unnormalized probs per row
    __shared__ float2 xs[NN];
    __shared__ float4 abcg[HH];

    int warp = threadIdx.x >> 5;
    int lane = threadIdx.x & 31;
    int row0 = blockIdx.x * TI;
    int row  = row0 + warp;

    for (int idx = threadIdx.x; idx < TI * HH; idx += 128)
        qs[idx >> 7][idx & 127] = g_q[row0 * HH + idx];
    for (int idx = threadIdx.x; idx < NN; idx += 128)
        xs[idx] = ((const float2*)xin)[idx];
    if (threadIdx.x < HH) abcg[threadIdx.x] = g_abcg[threadIdx.x];
    __syncthreads();

    const float4* q4 = (const float4*)&qs[warp][0];

    // ---- Phase 1: logits s[row][j] = q_row . k_j  (q pre-scaled) ----
    for (int jt = 0; jt < 32; ++jt) {
#pragma unroll
        for (int l = 0; l < 8; ++l) {
            int idx = threadIdx.x + l * 128;       // 0..1023 float4 slots
            int jr = idx >> 5, c4 = idx & 31;
            ((float4*)&kvs[jr][0])[c4] = ((const float4*)g_k)[(jt * 32 + jr) * 32 + c4];
        }
        __syncthreads();
        const float4* k4 = (const float4*)&kvs[lane][0];
        float a0 = 0.f, a1 = 0.f, a2 = 0.f, a3 = 0.f;
#pragma unroll
        for (int c4 = 0; c4 < 32; ++c4) {
            float4 kk = k4[c4];
            float4 qq = q4[c4];
            a0 = fmaf(qq.x, kk.x, a0);
            a1 = fmaf(qq.y, kk.y, a1);
            a2 = fmaf(qq.z, kk.z, a2);
            a3 = fmaf(qq.w, kk.w, a3);
        }
        ss[warp][jt * 32 + lane] = (a0 + a1) + (a2 + a3);
        __syncthreads();
    }

    // ---- Phase 2: softmax (keep unnormalized exp + 1/sum) ----
    float m = -3.4e38f;
#pragma unroll 4
    for (int t = 0; t < 32; ++t) m = fmaxf(m, ss[warp][t * 32 + lane]);
#pragma unroll
    for (int off = 16; off; off >>= 1) m = fmaxf(m, __shfl_xor_sync(0xffffffffu, m, off));
    float sum = 0.f;
#pragma unroll 4
    for (int t = 0; t < 32; ++t) {
        float e = __expf(ss[warp][t * 32 + lane] - m);
        ss[warp][t * 32 + lane] = e;
        sum += e;
    }
#pragma unroll
    for (int off = 16; off; off >>= 1) sum += __shfl_xor_sync(0xffffffffu, sum, off);
    float rinv = 1.f / sum;

    // ---- Phase 3: agg = P @ V ----
    float4 acc = make_float4(0.f, 0.f, 0.f, 0.f);
    for (int jt = 0; jt < 32; ++jt) {
        __syncthreads();   // previous tile fully consumed before overwrite
#pragma unroll
        for (int l = 0; l < 8; ++l) {
            int idx = threadIdx.x + l * 128;
            int jr = idx >> 5, c4 = idx & 31;
            ((float4*)&kvs[jr][0])[c4] = ((const float4*)g_v)[(jt * 32 + jr) * 32 + c4];
        }
        __syncthreads();
#pragma unroll 8
        for (int jj = 0; jj < 32; ++jj) {
            float p = ss[warp][jt * 32 + jj];
            float4 vv = ((const float4*)&kvs[jj][0])[lane];
            acc.x = fmaf(p, vv.x, acc.x);
            acc.y = fmaf(p, vv.y, acc.y);
            acc.z = fmaf(p, vv.z, acc.z);
            acc.w = fmaf(p, vv.w, acc.w);
        }
    }
    {
        float4 hv = ((const float4*)hin)[row * 32 + lane];
        float4 ho;
        ho.x = hv.x + acc.x * rinv;
        ho.y = hv.y + acc.y * rinv;
        ho.z = hv.z + acc.z * rinv;
        ho.w = hv.w + acc.w * rinv;
        ((float4*)out)[row * 32 + lane] = ho;
    }

    // ---- Phase 4: delta_x[row] = sum_j p_j * cw(dx,dy) * (dx,dy) ----
    float2 xi = xs[row];
    float dxa = 0.f, dya = 0.f;
    float c0 = g_c0d;
    for (int t = 0; t < 32; ++t) {
        int j = t * 32 + lane;
        float2 xj = xs[j];
        float dx = xi.x - xj.x;
        float dy = xi.y - xj.y;
        float cw0 = c0, cw1 = 0.f, cw2 = 0.f, cw3 = 0.f;
#pragma unroll
        for (int hh = 0; hh < HH; hh += 4) {
            float4 p0 = abcg[hh + 0];
            float4 p1 = abcg[hh + 1];
            float4 p2 = abcg[hh + 2];
            float4 p3 = abcg[hh + 3];
            float u0 = fmaf(p0.x, dx, fmaf(p0.y, dy, p0.z));
            float u1 = fmaf(p1.x, dx, fmaf(p1.y, dy, p1.z));
            float u2 = fmaf(p2.x, dx, fmaf(p2.y, dy, p2.z));
            float u3 = fmaf(p3.x, dx, fmaf(p3.y, dy, p3.z));
            cw0 = fmaf(fmaxf(u0, 0.f), p0.w, cw0);
            cw1 = fmaf(fmaxf(u1, 0.f), p1.w, cw1);
            cw2 = fmaf(fmaxf(u2, 0.f), p2.w, cw2);
            cw3 = fmaf(fmaxf(u3, 0.f), p3.w, cw3);
        }
        float cw = (cw0 + cw1) + (cw2 + cw3);
        float w = ss[warp][j] * cw;
        dxa = fmaf(w, dx, dxa);
        dya = fmaf(w, dy, dya);
    }
#pragma unroll
    for (int off = 16; off; off >>= 1) {
        dxa += __shfl_xor_sync(0xffffffffu, dxa, off);
        dya += __shfl_xor_sync(0xffffffffu, dya, off);
    }
    if (lane == 0) {
        float2 xo;
        xo.x = xi.x + dxa * rinv;
        xo.y = xi.y + dya * rinv;
        ((float2*)(out + NN * HH))[row] = xo;
    }
}

// ---------------------------------------------------------------------------
extern "C" void kernel_launch(void* const* d_in, const int* in_sizes, int n_in,
                              void* d_out, int out_size) {
    (void)in_sizes; (void)n_in; (void)out_size;
    const float* h   = (const float*)d_in[0];
    const float* x   = (const float*)d_in[1];
    // d_in[2] = batch (unused, all zeros in reference semantics)
    const float* Wq  = (const float*)d_in[3];
    const float* bq  = (const float*)d_in[4];
    const float* Wk  = (const float*)d_in[5];
    const float* bk  = (const float*)d_in[6];
    const float* Wv  = (const float*)d_in[7];
    const float* bv  = (const float*)d_in[8];
    const float* We1 = (const float*)d_in[9];
    const float* be1 = (const float*)d_in[10];
    const float* We2 = (const float*)d_in[11];
    const float* be2 = (const float*)d_in[12];
    const float* Wc  = (const float*)d_in[13];
    const float* bc  = (const float*)d_in[14];
    float* out = (float*)d_out;

    fold_kernel<<<1, 128>>>(We1, be1, We2, be2, Wc, bc);
    qkv_kernel<<<128, 384>>>(h, Wq, bq, Wk, bk, Wv, bv);
    attn_kernel<<<NN / TI, 128>>>(h, x, out);
}

// round 2
// speedup vs baseline: 1.9233x; 1.9233x over previous
#include <cuda_runtime.h>

#define NN 1024
#define HH 128

typedef unsigned long long u64;

union F2U { u64 u; float2 f; };

__device__ __forceinline__ u64 fma2(u64 a, u64 b, u64 c) {
    u64 d; asm("fma.rn.f32x2 %0, %1, %2, %3;" : "=l"(d) : "l"(a), "l"(b), "l"(c)); return d;
}
__device__ __forceinline__ u64 add2(u64 a, u64 b) {
    u64 d; asm("add.rn.f32x2 %0, %1, %2;" : "=l"(d) : "l"(a), "l"(b)); return d;
}
__device__ __forceinline__ u64 relu2(u64 a) {
    F2U t; t.u = a;
    t.f.x = fmaxf(t.f.x, 0.f);
    t.f.y = fmaxf(t.f.y, 0.f);
    return t.u;
}
__device__ __forceinline__ u64 pack2(float x, float y) {
    F2U t; t.f.x = x; t.f.y = y; return t.u;
}

// Scratch (device globals: no allocations allowed)
__device__ __align__(16) float g_q[NN * HH];
__device__ __align__(16) float g_k[NN * HH];
__device__ __align__(16) float g_v[NN * HH];
__device__ __align__(16) float g_p[NN * HH];     // p_h(i) = a*x + b*y + c
__device__ __align__(16) float g_rn[NN * HH];    // -r_h(j) = -(a*x + b*y)
__device__ __align__(16) float4 g_abcg[HH];
__device__ float g_c0d;

// ---------------------------------------------------------------------------
// Fold coord path:  coord_w[i,j] = sum_h relu(p_h(i) - r_h(j))*g_h + c0
//   g = Wc @ We2  (length H), c0 = Wc . be2 + bc
// 512 threads: 4 threads per h, shfl-reduced.
// ---------------------------------------------------------------------------
__global__ __launch_bounds__(512) void fold_kernel(
    const float* __restrict__ We1, const float* __restrict__ be1,
    const float* __restrict__ We2, const float* __restrict__ be2,
    const float* __restrict__ Wc,  const float* __restrict__ bc) {
    int h = threadIdx.x >> 2;
    int s = threadIdx.x & 3;
    float g = 0.f;
#pragma unroll 8
    for (int e = s * 32; e < s * 32 + 32; ++e)
        g = fmaf(Wc[e], We2[e * HH + h], g);
    g += __shfl_xor_sync(0xffffffffu, g, 1);
    g += __shfl_xor_sync(0xffffffffu, g, 2);
    if (s == 0)
        g_abcg[h] = make_float4(We1[h * 2 + 0], We1[h * 2 + 1], be1[h], g);
    if (threadIdx.x < 4) {
        float c0 = 0.f;
#pragma unroll 8
        for (int e = s * 32; e < s * 32 + 32; ++e)
            c0 = fmaf(Wc[e], be2[e], c0);
        c0 += __shfl_xor_sync(0xffffffffu, c0, 1);
        c0 += __shfl_xor_sync(0xffffffffu, c0, 2);
        if (threadIdx.x == 0) g_c0d = c0 + bc[0];
    }
}

// ---------------------------------------------------------------------------
// QKV + p/rneg: q = (h@Wq^T + bq)/sqrt(H),  k = h@Wk^T + bk,  v = h@Wv^T + bv
// 128 blocks x 8 rows, 384 threads.
// ---------------------------------------------------------------------------
__global__ __launch_bounds__(384) void qkv_kernel(
    const float* __restrict__ hin, const float* __restrict__ xin,
    const float* __restrict__ Wq, const float* __restrict__ bq,
    const float* __restrict__ Wk, const float* __restrict__ bk,
    const float* __restrict__ Wv, const float* __restrict__ bv) {
    __shared__ float hs[8][HH];
    int r0 = blockIdx.x * 8;
    for (int idx = threadIdx.x; idx < 8 * HH; idx += 384)
        hs[idx >> 7][idx & 127] = hin[r0 * HH + idx];
    __syncthreads();

    int o = threadIdx.x;
    const float* W; float bias; float* dst; int col; float scale;
    if (o < 128)      { W = Wq + o * HH;         bias = bq[o];       dst = g_q; col = o;       scale = 0.08838834764831845f; }
    else if (o < 256) { W = Wk + (o - 128) * HH; bias = bk[o - 128]; dst = g_k; col = o - 128; scale = 1.0f; }
    else              { W = Wv + (o - 256) * HH; bias = bv[o - 256]; dst = g_v; col = o - 256; scale = 1.0f; }

    float acc[8];
#pragma unroll
    for (int r = 0; r < 8; ++r) acc[r] = bias;

    const float4* W4 = (const float4*)W;
#pragma unroll 8
    for (int c4 = 0; c4 < 32; ++c4) {
        float4 w = W4[c4];
#pragma unroll
        for (int r = 0; r < 8; ++r) {
            float4 hv = ((const float4*)&hs[r][0])[c4];
            acc[r] = fmaf(hv.x, w.x, acc[r]);
            acc[r] = fmaf(hv.y, w.y, acc[r]);
            acc[r] = fmaf(hv.z, w.z, acc[r]);
            acc[r] = fmaf(hv.w, w.w, acc[r]);
        }
    }
#pragma unroll
    for (int r = 0; r < 8; ++r) dst[(r0 + r) * HH + col] = acc[r] * scale;

    // p / rneg for these 8 rows (threads 0..127, h = tid)
    if (o < HH) {
        float4 ab = g_abcg[o];
#pragma unroll
        for (int r = 0; r < 8; ++r) {
            int row = r0 + r;
            float xx = xin[2 * row], yy = xin[2 * row + 1];
            float base = fmaf(ab.x, xx, ab.y * yy);
            g_p[row * HH + o]  = base + ab.z;
            g_rn[row * HH + o] = -base;
        }
    }
}

// ---------------------------------------------------------------------------
// Fused attention + coord diffusion. One warp per output row, 4 rows/block.
// ---------------------------------------------------------------------------
__global__ __launch_bounds__(128) void attn_kernel(
    const float* __restrict__ hin,
    const float* __restrict__ xin,
    float* __restrict__ out) {
    __shared__ float  ss[4][NN];       // unnormalized probs per row (16 KB)
    __shared__ float  tile[32][132];   // k/v/rneg tile, padded (16.9 KB)
    __shared__ float2 xs[NN];          // (8 KB)
    __shared__ float  qs[4][132];      // (2.1 KB)
    __shared__ float4 pgs[4][64];      // (p_2h, p_2h+1, g_2h, g_2h+1) per row (4 KB)

    int warp = threadIdx.x >> 5;
    int lane = threadIdx.x & 31;
    int row0 = blockIdx.x * 4;
    int row  = row0 + warp;

    for (int idx = threadIdx.x; idx < 4 * HH; idx += 128)
        qs[idx >> 7][idx & 127] = g_q[row0 * HH + idx];
    for (int idx = threadIdx.x; idx < NN; idx += 128)
        xs[idx] = ((const float2*)xin)[idx];
    for (int idx = threadIdx.x; idx < 4 * 64; idx += 128) {
        int w = idx >> 6, hp = idx & 63;
        pgs[w][hp] = make_float4(g_p[(row0 + w) * HH + 2 * hp],
                                 g_p[(row0 + w) * HH + 2 * hp + 1],
                                 g_abcg[2 * hp].w, g_abcg[2 * hp + 1].w);
    }
    __syncthreads();

    const ulonglong2* q2 = (const ulonglong2*)&qs[warp][0];

    // ---- Phase 1: logits s[row][j] = q_row . k_j  (q pre-scaled) ----
    for (int jt = 0; jt < 32; ++jt) {
#pragma unroll
        for (int l = 0; l < 8; ++l) {
            int idx = threadIdx.x + l * 128;
            int jr = idx >> 5, c4 = idx & 31;
            ((float4*)&tile[jr][0])[c4] = ((const float4*)g_k)[(jt * 32 + jr) * 32 + c4];
        }
        __syncthreads();
        const ulonglong2* k2 = (const ulonglong2*)&tile[lane][0];
        u64 a0 = 0ull, a1 = 0ull;
#pragma unroll
        for (int c4 = 0; c4 < 32; ++c4) {
            ulonglong2 kk = k2[c4];
            ulonglong2 qq = q2[c4];
            a0 = fma2(qq.x, kk.x, a0);
            a1 = fma2(qq.y, kk.y, a1);
        }
        F2U ua, ub; ua.u = a0; ub.u = a1;
        ss[warp][jt * 32 + lane] = (ua.f.x + ua.f.y) + (ub.f.x + ub.f.y);
        __syncthreads();
    }

    // ---- Phase 2: softmax (keep unnormalized exp + 1/sum) ----
    float m = -3.4e38f;
#pragma unroll 4
    for (int t = 0; t < 32; ++t) m = fmaxf(m, ss[warp][t * 32 + lane]);
#pragma unroll
    for (int off = 16; off; off >>= 1) m = fmaxf(m, __shfl_xor_sync(0xffffffffu, m, off));
    float sum = 0.f;
#pragma unroll 4
    for (int t = 0; t < 32; ++t) {
        float e = __expf(ss[warp][t * 32 + lane] - m);
        ss[warp][t * 32 + lane] = e;
        sum += e;
    }
#pragma unroll
    for (int off = 16; off; off >>= 1) sum += __shfl_xor_sync(0xffffffffu, sum, off);
    float rinv = 1.f / sum;

    // ---- Phase 3: agg = P @ V ----
    u64 acc0 = 0ull, acc1 = 0ull;
    for (int jt = 0; jt < 32; ++jt) {
        __syncthreads();
#pragma unroll
        for (int l = 0; l < 8; ++l) {
            int idx = threadIdx.x + l * 128;
            int jr = idx >> 5, c4 = idx & 31;
            ((float4*)&tile[jr][0])[c4] = ((const float4*)g_v)[(jt * 32 + jr) * 32 + c4];
        }
        __syncthreads();
#pragma unroll 8
        for (int jj = 0; jj < 32; ++jj) {
            float p = ss[warp][jt * 32 + jj];
            u64 pp = pack2(p, p);
            ulonglong2 vv = ((const ulonglong2*)&tile[jj][0])[lane];
            acc0 = fma2(pp, vv.x, acc0);
            acc1 = fma2(pp, vv.y, acc1);
        }
    }
    {
        F2U a, b; a.u = acc0; b.u = acc1;
        float4 hv = ((const float4*)hin)[row * 32 + lane];
        float4 ho;
        ho.x = hv.x + a.f.x * rinv;
        ho.y = hv.y + a.f.y * rinv;
        ho.z = hv.z + b.f.x * rinv;
        ho.w = hv.w + b.f.y * rinv;
        ((float4*)out)[row * 32 + lane] = ho;
    }

    // ---- Phase 4: delta_x[row] = sum_j p_j * cw(i,j) * (dx,dy) ----
    //   cw(i,j) = sum_h relu(p_h(i) + rneg_h(j)) * g_h + c0
    float2 xi = xs[row];
    float dxa = 0.f, dya = 0.f;
    float c0 = g_c0d;
    for (int jt = 0; jt < 32; ++jt) {
        __syncthreads();
#pragma unroll
        for (int l = 0; l < 8; ++l) {
            int idx = threadIdx.x + l * 128;
            int jr = idx >> 5, c4 = idx & 31;
            ((float4*)&tile[jr][0])[c4] = ((const float4*)g_rn)[(jt * 32 + jr) * 32 + c4];
        }
        __syncthreads();
        const u64* r2 = (const u64*)&tile[lane][0];
        u64 cwa = 0ull, cwb = 0ull;
#pragma unroll 16
        for (int hp = 0; hp < 64; hp += 2) {
            float4 pg0 = pgs[warp][hp];
            float4 pg1 = pgs[warp][hp + 1];
            u64 u0 = relu2(add2(pack2(pg0.x, pg0.y), r2[hp]));
            u64 u1 = relu2(add2(pack2(pg1.x, pg1.y), r2[hp + 1]));
            cwa = fma2(u0, pack2(pg0.z, pg0.w), cwa);
            cwb = fma2(u1, pack2(pg1.z, pg1.w), cwb);
        }
        F2U ca, cb; ca.u = cwa; cb.u = cwb;
        float cw = c0 + (ca.f.x + ca.f.y) + (cb.f.x + cb.f.y);
        int j = jt * 32 + lane;
        float2 xj = xs[j];
        float dx = xi.x - xj.x;
        float dy = xi.y - xj.y;
        float w = ss[warp][j] * cw;
        dxa = fmaf(w, dx, dxa);
        dya = fmaf(w, dy, dya);
    }
#pragma unroll
    for (int off = 16; off; off >>= 1) {
        dxa += __shfl_xor_sync(0xffffffffu, dxa, off);
        dya += __shfl_xor_sync(0xffffffffu, dya, off);
    }
    if (lane == 0) {
        float2 xo;
        xo.x = xi.x + dxa * rinv;
        xo.y = xi.y + dya * rinv;
        ((float2*)(out + NN * HH))[row] = xo;
    }
}

// ---------------------------------------------------------------------------
extern "C" void kernel_launch(void* const* d_in, const int* in_sizes, int n_in,
                              void* d_out, int out_size) {
    (void)in_sizes; (void)n_in; (void)out_size;
    const float* h   = (const float*)d_in[0];
    const float* x   = (const float*)d_in[1];
    // d_in[2] = batch (unused, all zeros)
    const float* Wq  = (const float*)d_in[3];
    const float* bq  = (const float*)d_in[4];
    const float* Wk  = (const float*)d_in[5];
    const float* bk  = (const float*)d_in[6];
    const float* Wv  = (const float*)d_in[7];
    const float* bv  = (const float*)d_in[8];
    const float* We1 = (const float*)d_in[9];
    const float* be1 = (const float*)d_in[10];
    const float* We2 = (const float*)d_in[11];
    const float* be2 = (const float*)d_in[12];
    const float* Wc  = (const float*)d_in[13];
    const float* bc  = (const float*)d_in[14];
    float* out = (float*)d_out;

    fold_kernel<<<1, 512>>>(We1, be1, We2, be2, Wc, bc);
    qkv_kernel<<<128, 384>>>(h, x, Wq, bq, Wk, bk, Wv, bv);
    attn_kernel<<<NN / 4, 128>>>(h, x, out);
}